// round 1
// baseline (speedup 1.0000x reference)
#include <cuda_runtime.h>

// ---------------- problem constants ----------------
constexpr int B_  = 65536;
constexpr int D_  = 256;
constexpr int W1ROWS = 512, F1 = 16, W1PAD = 18;  // att_w1 rows padded 16->18 floats
constexpr int P1ROWS = 768, F2 = 8,  P1PAD = 10;  // pred_w1 rows padded 8->10 floats

constexpr int TPB  = 384;           // 12 warps / block
constexpr int WPB  = TPB / 32;
constexpr int GRID = 296;           // persistent-ish: 2 waves at 1 block/SM

// dynamic shared layout (float offsets)
constexpr int OFF_W1  = 0;                        // 512*18 = 9216
constexpr int OFF_P1  = OFF_W1 + W1ROWS * W1PAD;  // 9216
constexpr int OFF_B1  = OFF_P1 + P1ROWS * P1PAD;  // +7680 = 16896
constexpr int OFF_W2  = OFF_B1 + 16;
constexpr int OFF_PB1 = OFF_W2 + 16;
constexpr int OFF_PW2 = OFF_PB1 + 8;
constexpr int OFF_SC  = OFF_PW2 + 8;
constexpr int SMEM_FLOATS = OFF_SC + 8;           // 16952
constexpr int SMEM_BYTES  = SMEM_FLOATS * 4;      // ~67.8 KB

// ---------------- packed f32x2 helpers ----------------
__device__ __forceinline__ unsigned long long splat2(float x) {
    unsigned long long r;
    asm("mov.b64 %0, {%1, %1};" : "=l"(r) : "f"(x));
    return r;
}
__device__ __forceinline__ void ffma2(unsigned long long& d, unsigned long long a, unsigned long long b) {
    asm("fma.rn.f32x2 %0, %1, %2, %0;" : "+l"(d) : "l"(a), "l"(b));
}
__device__ __forceinline__ float lo2(unsigned long long v) { return __uint_as_float((unsigned)v); }
__device__ __forceinline__ float hi2(unsigned long long v) { return __uint_as_float((unsigned)(v >> 32)); }

__device__ __forceinline__ float warpsum(float v) {
    v += __shfl_xor_sync(0xffffffffu, v, 16);
    v += __shfl_xor_sync(0xffffffffu, v, 8);
    v += __shfl_xor_sync(0xffffffffu, v, 4);
    v += __shfl_xor_sync(0xffffffffu, v, 2);
    v += __shfl_xor_sync(0xffffffffu, v, 1);
    return v;
}

// Distributed reduce: each lane holds p[0..15] (partials over its e-slice for f=0..15).
// Returns the FULL 32-lane sum for f = (lane>>1)&15 (each f replicated on 2 lanes).
// Cost: 16 shfl instead of 80.
__device__ __forceinline__ float dreduce16(float* p, unsigned lane) {
    const unsigned FULL = 0xffffffffu;
    const bool b4 = (lane & 16), b3 = (lane & 8), b2 = (lane & 4), b1 = (lane & 2);
#pragma unroll
    for (int j = 0; j < 8; j++) {
        float send = b4 ? p[j] : p[j + 8];
        float r = __shfl_xor_sync(FULL, send, 16);
        p[j] = (b4 ? p[j + 8] : p[j]) + r;
    }
#pragma unroll
    for (int j = 0; j < 4; j++) {
        float send = b3 ? p[j] : p[j + 4];
        float r = __shfl_xor_sync(FULL, send, 8);
        p[j] = (b3 ? p[j + 4] : p[j]) + r;
    }
#pragma unroll
    for (int j = 0; j < 2; j++) {
        float send = b2 ? p[j] : p[j + 2];
        float r = __shfl_xor_sync(FULL, send, 4);
        p[j] = (b2 ? p[j + 2] : p[j]) + r;
    }
    {
        float send = b1 ? p[0] : p[1];
        float r = __shfl_xor_sync(FULL, send, 2);
        p[0] = (b1 ? p[1] : p[0]) + r;
    }
    p[0] += __shfl_xor_sync(FULL, p[0], 1);
    return p[0];
}

// Same idea for 8 values: returns full sum for o = (lane>>2)&7 (each o on 4 lanes).
__device__ __forceinline__ float dreduce8(float* p, unsigned lane) {
    const unsigned FULL = 0xffffffffu;
    const bool b4 = (lane & 16), b3 = (lane & 8), b2 = (lane & 4);
#pragma unroll
    for (int j = 0; j < 4; j++) {
        float send = b4 ? p[j] : p[j + 4];
        float r = __shfl_xor_sync(FULL, send, 16);
        p[j] = (b4 ? p[j + 4] : p[j]) + r;
    }
#pragma unroll
    for (int j = 0; j < 2; j++) {
        float send = b3 ? p[j] : p[j + 2];
        float r = __shfl_xor_sync(FULL, send, 8);
        p[j] = (b3 ? p[j + 2] : p[j]) + r;
    }
    {
        float send = b2 ? p[0] : p[1];
        float r = __shfl_xor_sync(FULL, send, 4);
        p[0] = (b2 ? p[1] : p[0]) + r;
    }
    p[0] += __shfl_xor_sync(FULL, p[0], 2);
    p[0] += __shfl_xor_sync(FULL, p[0], 1);
    return p[0];
}

__global__ __launch_bounds__(TPB, 1) void agree_kernel(
    const int*   __restrict__ group_inputs,
    const int*   __restrict__ item_inputs,
    const int*   __restrict__ group_members,
    const float* __restrict__ user_emb,
    const float* __restrict__ item_emb,
    const float* __restrict__ group_emb,
    const float* __restrict__ att_w1,
    const float* __restrict__ att_b1,
    const float* __restrict__ att_w2,
    const float* __restrict__ att_b2,
    const float* __restrict__ cls_w,
    const float* __restrict__ cls_b,
    const float* __restrict__ pred_w1,
    const float* __restrict__ pred_b1,
    const float* __restrict__ pred_w2,
    const float* __restrict__ pred_b2,
    float* __restrict__ out)
{
    extern __shared__ float sm[];
    float* s_w1  = sm + OFF_W1;
    float* s_p1  = sm + OFF_P1;
    float* s_b1  = sm + OFF_B1;
    float* s_w2  = sm + OFF_W2;
    float* s_pb1 = sm + OFF_PB1;
    float* s_pw2 = sm + OFF_PW2;
    float* s_sc  = sm + OFF_SC;

    const int tid = threadIdx.x;

    // stage weights (padded rows for bank-conflict-free strided LDS.64)
    for (int i = tid; i < W1ROWS * F1; i += TPB) s_w1[(i >> 4) * W1PAD + (i & 15)] = att_w1[i];
    for (int i = tid; i < P1ROWS * F2; i += TPB) s_p1[(i >> 3) * P1PAD + (i & 7)] = pred_w1[i];
    if (tid < 16) { s_b1[tid] = att_b1[tid]; s_w2[tid] = att_w2[tid]; }
    if (tid < 8)  { s_pb1[tid] = pred_b1[tid]; s_pw2[tid] = pred_w2[tid]; }
    if (tid == 0) {
        s_sc[0] = att_b2[0]; s_sc[1] = pred_b2[0];
        s_sc[2] = cls_w[0];  s_sc[3] = cls_w[1];
        s_sc[4] = cls_b[0];  s_sc[5] = cls_b[1];
    }
    __syncthreads();

    const unsigned lane = tid & 31;
    const int warp = tid >> 5;
    const int fidx = (int)((lane >> 1) & 15);
    const int oidx = (int)((lane >> 2) & 7);
    const float b1v  = s_b1[fidx];
    const float w2v  = s_w2[fidx];
    const float pb1v = s_pb1[oidx];
    const float pw2v = s_pw2[oidx];
    const float attb2 = s_sc[0], predb2 = s_sc[1];
    const float clsd  = s_sc[3] - s_sc[2];   // cls_w[0][1] - cls_w[0][0]
    const float clsbd = s_sc[5] - s_sc[4];   // cls_b[1]    - cls_b[0]

    for (int b = blockIdx.x * WPB + warp; b < B_; b += GRID * WPB) {
        const int gid = group_inputs[b];
        const int iid = item_inputs[b];
        const int4 mi4 = *reinterpret_cast<const int4*>(group_members + (size_t)gid * 4);

        // gather: coalesced, lane owns e in {lane+32k}
        const float* u0 = user_emb + (size_t)mi4.x * D_ + lane;
        const float* u1 = user_emb + (size_t)mi4.y * D_ + lane;
        const float* u2 = user_emb + (size_t)mi4.z * D_ + lane;
        const float* u3 = user_emb + (size_t)mi4.w * D_ + lane;
        const float* ip = item_emb + (size_t)iid   * D_ + lane;

        float m0[8], m1[8], m2[8], m3[8], it[8];
#pragma unroll
        for (int k = 0; k < 8; k++) {
            m0[k] = u0[32 * k]; m1[k] = u1[32 * k];
            m2[k] = u2[32 * k]; m3[k] = u3[32 * k];
            it[k] = ip[32 * k];
        }

        // ---- attention MLP: h = relu(gi @ att_w1 + b1) ----
        // member weight rows read ONCE per b, FMA'd into 4 member accumulators.
        unsigned long long acc0[8], acc1[8], acc2[8], acc3[8], iacc[8];
#pragma unroll
        for (int fp = 0; fp < 8; fp++) { acc0[fp] = 0; acc1[fp] = 0; acc2[fp] = 0; acc3[fp] = 0; iacc[fp] = 0; }

#pragma unroll
        for (int k = 0; k < 8; k++) {
            const int e = (int)lane + 32 * k;
            const float* wr  = s_w1 + e * W1PAD;          // member half rows [0,256)
            const float* wr2 = wr + 256 * W1PAD;          // item half rows [256,512)
            const unsigned long long v0 = splat2(m0[k]);
            const unsigned long long v1 = splat2(m1[k]);
            const unsigned long long v2 = splat2(m2[k]);
            const unsigned long long v3 = splat2(m3[k]);
            const unsigned long long vi = splat2(it[k]);
#pragma unroll
            for (int fp = 0; fp < 8; fp++) {
                const unsigned long long w = *reinterpret_cast<const unsigned long long*>(wr + 2 * fp);
                ffma2(acc0[fp], v0, w);
                ffma2(acc1[fp], v1, w);
                ffma2(acc2[fp], v2, w);
                ffma2(acc3[fp], v3, w);
                const unsigned long long wI = *reinterpret_cast<const unsigned long long*>(wr2 + 2 * fp);
                ffma2(iacc[fp], vi, wI);
            }
        }

        float logits[4];
#pragma unroll
        for (int s = 0; s < 4; s++) {
            const unsigned long long* a = (s == 0) ? acc0 : (s == 1) ? acc1 : (s == 2) ? acc2 : acc3;
            float p[16];
#pragma unroll
            for (int fp = 0; fp < 8; fp++) {
                p[2 * fp]     = lo2(a[fp]) + lo2(iacc[fp]);
                p[2 * fp + 1] = hi2(a[fp]) + hi2(iacc[fp]);
            }
            const float hs = dreduce16(p, lane);
            const float h = fmaxf(hs + b1v, 0.0f);
            // each f lives on 2 lanes -> warpsum double-counts by 2
            logits[s] = 0.5f * warpsum(h * w2v) + attb2;
        }

        // softmax + first-argmax (matches jnp.argmax tie rule via strict >)
        float mx = logits[0]; int mi = 0;
#pragma unroll
        for (int s = 1; s < 4; s++) if (logits[s] > mx) { mx = logits[s]; mi = s; }
        const float e0 = __expf(logits[0] - mx), e1 = __expf(logits[1] - mx);
        const float e2 = __expf(logits[2] - mx), e3 = __expf(logits[3] - mx);
        const float inv = 1.0f / (e0 + e1 + e2 + e3);
        const float wt0 = e0 * inv, wt1 = e1 * inv, wt2 = e2 * inv, wt3 = e3 * inv;
        const float wmx = (mi == 0) ? wt0 : (mi == 1) ? wt1 : (mi == 2) ? wt2 : wt3;
        const bool pc = (wmx * clsd + clsbd) > 0.0f;  // class 1 iff score1 > score0

        // g = (leader | weighted) + group_emb ; elem = g * item
        const float* ge = group_emb + (size_t)gid * D_ + lane;
        float g[8], el[8];
#pragma unroll
        for (int k = 0; k < 8; k++) {
            const float ws = wt0 * m0[k] + wt1 * m1[k] + wt2 * m2[k] + wt3 * m3[k];
            const float ld = (mi == 0) ? m0[k] : (mi == 1) ? m1[k] : (mi == 2) ? m2[k] : m3[k];
            g[k]  = (pc ? ld : ws) + ge[32 * k];
            el[k] = g[k] * it[k];
        }

        // ---- prediction MLP: sigmoid(relu([elem,g,item] @ pred_w1 + b1) @ pred_w2 + b2) ----
        unsigned long long pa[4] = {0, 0, 0, 0};
#pragma unroll
        for (int k = 0; k < 8; k++) {
            const int e = (int)lane + 32 * k;
            const float* r0 = s_p1 + e * P1PAD;       // elem rows [0,256)
            const float* r1 = r0 + 256 * P1PAD;       // g rows    [256,512)
            const float* r2 = r1 + 256 * P1PAD;       // item rows [512,768)
            const unsigned long long ve = splat2(el[k]);
            const unsigned long long vg = splat2(g[k]);
            const unsigned long long vi = splat2(it[k]);
#pragma unroll
            for (int op = 0; op < 4; op++) {
                ffma2(pa[op], ve, *reinterpret_cast<const unsigned long long*>(r0 + 2 * op));
                ffma2(pa[op], vg, *reinterpret_cast<const unsigned long long*>(r1 + 2 * op));
                ffma2(pa[op], vi, *reinterpret_cast<const unsigned long long*>(r2 + 2 * op));
            }
        }
        float q[8];
#pragma unroll
        for (int op = 0; op < 4; op++) { q[2 * op] = lo2(pa[op]); q[2 * op + 1] = hi2(pa[op]); }
        const float ps = dreduce8(q, lane);
        const float h2 = fmaxf(ps + pb1v, 0.0f);
        // each o lives on 4 lanes -> warpsum quadruple-counts
        const float z = 0.25f * warpsum(h2 * pw2v) + predb2;
        const float y = 1.0f / (1.0f + __expf(-z));

        if (lane == 0) {
            out[b] = y;
            out[5 * B_ + b] = pc ? 1.0f : 0.0f;
        }
        if (lane < 4) {
            const float w = (lane == 0) ? wt0 : (lane == 1) ? wt1 : (lane == 2) ? wt2 : wt3;
            out[B_ + 4 * b + (int)lane] = w;
        }
    }
}

extern "C" void kernel_launch(void* const* d_in, const int* in_sizes, int n_in,
                              void* d_out, int out_size) {
    cudaFuncSetAttribute(agree_kernel, cudaFuncAttributeMaxDynamicSharedMemorySize, SMEM_BYTES);
    agree_kernel<<<GRID, TPB, SMEM_BYTES>>>(
        (const int*)d_in[0], (const int*)d_in[1], (const int*)d_in[2],
        (const float*)d_in[3], (const float*)d_in[4], (const float*)d_in[5],
        (const float*)d_in[6], (const float*)d_in[7], (const float*)d_in[8], (const float*)d_in[9],
        (const float*)d_in[10], (const float*)d_in[11], (const float*)d_in[12], (const float*)d_in[13],
        (const float*)d_in[14], (const float*)d_in[15],
        (float*)d_out);
}

// round 3
// speedup vs baseline: 2.6159x; 2.6159x over previous
#include <cuda_runtime.h>

// ---------------- problem constants ----------------
constexpr int B_  = 65536;
constexpr int D_  = 256;
constexpr int W1ROWS = 512, F1 = 16, W1PAD = 18;  // even pad: 8B-aligned LDS.64; stride 9 words, gcd(9,16)=1 -> conflict-free
constexpr int P1ROWS = 768, F2 = 8,  P1PAD = 10;  // stride 5 words, gcd(5,16)=1 -> conflict-free

constexpr int TPB  = 256;           // 8 warps / block
constexpr int WPB  = TPB / 32;
constexpr int GRID = 296;           // 2 blocks/SM resident -> 1 wave

// dynamic shared layout (float offsets)
constexpr int OFF_W1  = 0;                        // 512*18 = 9216
constexpr int OFF_P1  = OFF_W1 + W1ROWS * W1PAD;  // 9216
constexpr int OFF_B1  = OFF_P1 + P1ROWS * P1PAD;  // +7680 = 16896
constexpr int OFF_W2  = OFF_B1 + 16;
constexpr int OFF_PB1 = OFF_W2 + 16;
constexpr int OFF_PW2 = OFF_PB1 + 8;
constexpr int OFF_SC  = OFF_PW2 + 8;
constexpr int SMEM_FLOATS = OFF_SC + 8;           // 16952
constexpr int SMEM_BYTES  = SMEM_FLOATS * 4;      // ~67.8 KB; 2 blocks = 135.6KB/SM, fits

// ---------------- packed f32x2 helpers ----------------
__device__ __forceinline__ unsigned long long splat2(float x) {
    unsigned long long r;
    asm("mov.b64 %0, {%1, %1};" : "=l"(r) : "f"(x));
    return r;
}
__device__ __forceinline__ void ffma2(unsigned long long& d, unsigned long long a, unsigned long long b) {
    asm("fma.rn.f32x2 %0, %1, %2, %0;" : "+l"(d) : "l"(a), "l"(b));
}
__device__ __forceinline__ float lo2(unsigned long long v) { return __uint_as_float((unsigned)v); }
__device__ __forceinline__ float hi2(unsigned long long v) { return __uint_as_float((unsigned)(v >> 32)); }

// Distributed reduce over 8 values: each lane holds p[0..7] (partials over its
// e-slice for 8 outputs). Returns the FULL 32-lane sum for o = (lane>>2)&7
// (replicated identically on the 4 lanes of each o-group). 11 shuffles.
__device__ __forceinline__ float dreduce8(float* p, unsigned lane) {
    const unsigned FULL = 0xffffffffu;
    const bool b4 = (lane & 16), b3 = (lane & 8), b2 = (lane & 4);
#pragma unroll
    for (int j = 0; j < 4; j++) {
        float send = b4 ? p[j] : p[j + 4];
        float r = __shfl_xor_sync(FULL, send, 16);
        p[j] = (b4 ? p[j + 4] : p[j]) + r;
    }
#pragma unroll
    for (int j = 0; j < 2; j++) {
        float send = b3 ? p[j] : p[j + 2];
        float r = __shfl_xor_sync(FULL, send, 8);
        p[j] = (b3 ? p[j + 2] : p[j]) + r;
    }
    {
        float send = b2 ? p[0] : p[1];
        float r = __shfl_xor_sync(FULL, send, 4);
        p[0] = (b2 ? p[1] : p[0]) + r;
    }
    p[0] += __shfl_xor_sync(FULL, p[0], 2);
    p[0] += __shfl_xor_sync(FULL, p[0], 1);
    return p[0];
}

// Sum across the 8 o-groups (lane bits 2..4); input identical within each
// 4-lane o-group; result identical on all lanes.
__device__ __forceinline__ float xsum3(float v) {
    v += __shfl_xor_sync(0xffffffffu, v, 4);
    v += __shfl_xor_sync(0xffffffffu, v, 8);
    v += __shfl_xor_sync(0xffffffffu, v, 16);
    return v;
}

__global__ __launch_bounds__(TPB, 2) void agree_kernel(
    const int*   __restrict__ group_inputs,
    const int*   __restrict__ item_inputs,
    const int*   __restrict__ group_members,
    const float* __restrict__ user_emb,
    const float* __restrict__ item_emb,
    const float* __restrict__ group_emb,
    const float* __restrict__ att_w1,
    const float* __restrict__ att_b1,
    const float* __restrict__ att_w2,
    const float* __restrict__ att_b2,
    const float* __restrict__ cls_w,
    const float* __restrict__ cls_b,
    const float* __restrict__ pred_w1,
    const float* __restrict__ pred_b1,
    const float* __restrict__ pred_w2,
    const float* __restrict__ pred_b2,
    float* __restrict__ out)
{
    extern __shared__ float sm[];
    float* s_w1  = sm + OFF_W1;
    float* s_p1  = sm + OFF_P1;
    float* s_b1  = sm + OFF_B1;
    float* s_w2  = sm + OFF_W2;
    float* s_pb1 = sm + OFF_PB1;
    float* s_pw2 = sm + OFF_PW2;
    float* s_sc  = sm + OFF_SC;

    const int tid = threadIdx.x;

    // stage weights (even-padded rows: aligned + conflict-free)
    for (int i = tid; i < W1ROWS * F1; i += TPB) s_w1[(i >> 4) * W1PAD + (i & 15)] = att_w1[i];
    for (int i = tid; i < P1ROWS * F2; i += TPB) s_p1[(i >> 3) * P1PAD + (i & 7)] = pred_w1[i];
    if (tid < 16) { s_b1[tid] = att_b1[tid]; s_w2[tid] = att_w2[tid]; }
    if (tid < 8)  { s_pb1[tid] = pred_b1[tid]; s_pw2[tid] = pred_w2[tid]; }
    if (tid == 0) {
        s_sc[0] = att_b2[0]; s_sc[1] = pred_b2[0];
        s_sc[2] = cls_w[0];  s_sc[3] = cls_w[1];
        s_sc[4] = cls_b[0];  s_sc[5] = cls_b[1];
    }
    __syncthreads();

    const unsigned lane = tid & 31;
    const int warp = tid >> 5;
    const int oidx = (int)((lane >> 2) & 7);
    const float b1v0 = s_b1[oidx],  b1v1 = s_b1[8 + oidx];
    const float w2v0 = s_w2[oidx],  w2v1 = s_w2[8 + oidx];
    const float pb1v = s_pb1[oidx], pw2v = s_pw2[oidx];
    const float attb2 = s_sc[0], predb2 = s_sc[1];
    const float clsd  = s_sc[3] - s_sc[2];   // cls_w[0][1] - cls_w[0][0]
    const float clsbd = s_sc[5] - s_sc[4];   // cls_b[1]    - cls_b[0]

    const int stride = GRID * WPB;
    int b = blockIdx.x * WPB + warp;

    // ---- pipeline prologue: indices + member/item rows for first b ----
    int gid = group_inputs[b];
    int iid = item_inputs[b];
    {
        // first-b member/item rows
    }
    int4 mi4 = *reinterpret_cast<const int4*>(group_members + (size_t)gid * 4);

    float m0[8], m1[8], m2[8], m3[8], it[8];
    {
        const float* u0 = user_emb + (size_t)mi4.x * D_ + lane;
        const float* u1 = user_emb + (size_t)mi4.y * D_ + lane;
        const float* u2 = user_emb + (size_t)mi4.z * D_ + lane;
        const float* u3 = user_emb + (size_t)mi4.w * D_ + lane;
        const float* ip = item_emb + (size_t)iid   * D_ + lane;
#pragma unroll
        for (int k = 0; k < 8; k++) {
            m0[k] = u0[32 * k]; m1[k] = u1[32 * k];
            m2[k] = u2[32 * k]; m3[k] = u3[32 * k];
            it[k] = ip[32 * k];
        }
    }

    while (true) {
        // group-row load issued early (latency covered by attention phase)
        const float* gep = group_emb + (size_t)gid * D_ + lane;
        float ge[8];
#pragma unroll
        for (int k = 0; k < 8; k++) ge[k] = gep[32 * k];

        // prefetch next-b index chain (overlaps attention FFMA phase)
        const int bn = b + stride;
        const bool has_next = (bn < B_);
        int ngid = 0, niid = 0;
        int4 nmi4 = make_int4(0, 0, 0, 0);
        if (has_next) {
            ngid = group_inputs[bn];
            niid = item_inputs[bn];
            nmi4 = *reinterpret_cast<const int4*>(group_members + (size_t)ngid * 4);
        }

        // ---- attention MLP in two feature halves (f = 8H + [0,8)) ----
        float lp0 = 0.f, lp1 = 0.f, lp2 = 0.f, lp3 = 0.f;
#pragma unroll
        for (int H = 0; H < 2; H++) {
            unsigned long long a0[4], a1[4], a2[4], a3[4], ia[4];
#pragma unroll
            for (int fp = 0; fp < 4; fp++) { a0[fp] = 0; a1[fp] = 0; a2[fp] = 0; a3[fp] = 0; ia[fp] = 0; }
#pragma unroll
            for (int k = 0; k < 8; k++) {
                const int e = (int)lane + 32 * k;
                const float* wr  = s_w1 + e * W1PAD + 8 * H;   // member half rows [0,256)
                const float* wr2 = wr + 256 * W1PAD;           // item half rows [256,512)
                const unsigned long long v0 = splat2(m0[k]);
                const unsigned long long v1 = splat2(m1[k]);
                const unsigned long long v2 = splat2(m2[k]);
                const unsigned long long v3 = splat2(m3[k]);
                const unsigned long long vi = splat2(it[k]);
#pragma unroll
                for (int fp = 0; fp < 4; fp++) {
                    const unsigned long long w = *reinterpret_cast<const unsigned long long*>(wr + 2 * fp);
                    ffma2(a0[fp], v0, w);
                    ffma2(a1[fp], v1, w);
                    ffma2(a2[fp], v2, w);
                    ffma2(a3[fp], v3, w);
                    const unsigned long long wI = *reinterpret_cast<const unsigned long long*>(wr2 + 2 * fp);
                    ffma2(ia[fp], vi, wI);
                }
            }
            const float b1v = H ? b1v1 : b1v0;
            const float w2v = H ? w2v1 : w2v0;
#pragma unroll
            for (int s = 0; s < 4; s++) {
                const unsigned long long* a = (s == 0) ? a0 : (s == 1) ? a1 : (s == 2) ? a2 : a3;
                float p[8];
#pragma unroll
                for (int fp = 0; fp < 4; fp++) {
                    p[2 * fp]     = lo2(a[fp]) + lo2(ia[fp]);
                    p[2 * fp + 1] = hi2(a[fp]) + hi2(ia[fp]);
                }
                const float hs = dreduce8(p, lane);
                const float h = fmaxf(hs + b1v, 0.0f);
                const float c = h * w2v;
                if      (s == 0) lp0 += c;
                else if (s == 1) lp1 += c;
                else if (s == 2) lp2 += c;
                else             lp3 += c;
            }
        }
        float logits[4];
        logits[0] = xsum3(lp0) + attb2;
        logits[1] = xsum3(lp1) + attb2;
        logits[2] = xsum3(lp2) + attb2;
        logits[3] = xsum3(lp3) + attb2;

        // softmax + first-argmax (strict > matches jnp.argmax tie rule)
        float mx = logits[0]; int mi = 0;
#pragma unroll
        for (int s = 1; s < 4; s++) if (logits[s] > mx) { mx = logits[s]; mi = s; }
        const float e0 = __expf(logits[0] - mx), e1 = __expf(logits[1] - mx);
        const float e2 = __expf(logits[2] - mx), e3 = __expf(logits[3] - mx);
        const float inv = 1.0f / (e0 + e1 + e2 + e3);
        const float wt0 = e0 * inv, wt1 = e1 * inv, wt2 = e2 * inv, wt3 = e3 * inv;
        const float wmx = (mi == 0) ? wt0 : (mi == 1) ? wt1 : (mi == 2) ? wt2 : wt3;
        const bool pc = (wmx * clsd + clsbd) > 0.0f;

        // g = (leader | weighted) + group_emb  (last use of m0..m3)
        float g[8];
#pragma unroll
        for (int k = 0; k < 8; k++) {
            const float ws = wt0 * m0[k] + wt1 * m1[k] + wt2 * m2[k] + wt3 * m3[k];
            const float ld = (mi == 0) ? m0[k] : (mi == 1) ? m1[k] : (mi == 2) ? m2[k] : m3[k];
            g[k] = (pc ? ld : ws) + ge[k];
        }

        // ---- issue next-b row loads NOW (m regs dead; overlaps pred MLP) ----
        float nit[8];
        if (has_next) {
            const float* u0 = user_emb + (size_t)nmi4.x * D_ + lane;
            const float* u1 = user_emb + (size_t)nmi4.y * D_ + lane;
            const float* u2 = user_emb + (size_t)nmi4.z * D_ + lane;
            const float* u3 = user_emb + (size_t)nmi4.w * D_ + lane;
            const float* ip = item_emb + (size_t)niid   * D_ + lane;
#pragma unroll
            for (int k = 0; k < 8; k++) {
                m0[k] = u0[32 * k]; m1[k] = u1[32 * k];
                m2[k] = u2[32 * k]; m3[k] = u3[32 * k];
                nit[k] = ip[32 * k];
            }
        }

        // ---- prediction MLP: sigmoid(relu([g*it, g, it] @ pred_w1 + b1) @ pred_w2 + b2) ----
        unsigned long long pa[4] = {0, 0, 0, 0};
#pragma unroll
        for (int k = 0; k < 8; k++) {
            const int e = (int)lane + 32 * k;
            const float* r0 = s_p1 + e * P1PAD;       // elem rows [0,256)
            const float* r1 = r0 + 256 * P1PAD;       // g rows    [256,512)
            const float* r2 = r1 + 256 * P1PAD;       // item rows [512,768)
            const unsigned long long ve = splat2(g[k] * it[k]);
            const unsigned long long vg = splat2(g[k]);
            const unsigned long long vi = splat2(it[k]);
#pragma unroll
            for (int op = 0; op < 4; op++) {
                ffma2(pa[op], ve, *reinterpret_cast<const unsigned long long*>(r0 + 2 * op));
                ffma2(pa[op], vg, *reinterpret_cast<const unsigned long long*>(r1 + 2 * op));
                ffma2(pa[op], vi, *reinterpret_cast<const unsigned long long*>(r2 + 2 * op));
            }
        }
        float q[8];
#pragma unroll
        for (int op = 0; op < 4; op++) { q[2 * op] = lo2(pa[op]); q[2 * op + 1] = hi2(pa[op]); }
        const float ps = dreduce8(q, lane);
        const float h2 = fmaxf(ps + pb1v, 0.0f);
        const float z = xsum3(h2 * pw2v) + predb2;
        const float y = 1.0f / (1.0f + __expf(-z));

        if (lane == 0) {
            out[b] = y;
            out[5 * B_ + b] = pc ? 1.0f : 0.0f;
        }
        if (lane < 4) {
            const float w = (lane == 0) ? wt0 : (lane == 1) ? wt1 : (lane == 2) ? wt2 : wt3;
            out[B_ + 4 * b + (int)lane] = w;
        }

        if (!has_next) break;
#pragma unroll
        for (int k = 0; k < 8; k++) it[k] = nit[k];
        gid = ngid; iid = niid; b = bn;
    }
}

extern "C" void kernel_launch(void* const* d_in, const int* in_sizes, int n_in,
                              void* d_out, int out_size) {
    cudaFuncSetAttribute(agree_kernel, cudaFuncAttributeMaxDynamicSharedMemorySize, SMEM_BYTES);
    agree_kernel<<<GRID, TPB, SMEM_BYTES>>>(
        (const int*)d_in[0], (const int*)d_in[1], (const int*)d_in[2],
        (const float*)d_in[3], (const float*)d_in[4], (const float*)d_in[5],
        (const float*)d_in[6], (const float*)d_in[7], (const float*)d_in[8], (const float*)d_in[9],
        (const float*)d_in[10], (const float*)d_in[11], (const float*)d_in[12], (const float*)d_in[13],
        (const float*)d_in[14], (const float*)d_in[15],
        (float*)d_out);
}